// round 12
// baseline (speedup 1.0000x reference)
#include <cuda_runtime.h>
#include <stdint.h>

// Problem constants (fixed by the dataset problem).
#define HH 112
#define WW 112
#define HW (HH * WW)
#define MAXB 4   // scratch sized for up to 4 batches

// Planar per-pixel per-channel winner keys:
//   high 32 = order-preserving encoded flat depth
//   low  32 = raw float bits of that triangle's flat color for this channel
// atomicMax (return discarded -> REDG) selects max-depth triangle; payload
// rides along. 0 = "uncovered". Zero-initialized at module load; resolve
// re-zeros after consuming (invariant across graph replays) — no init kernel.
__device__ unsigned long long g_kr[MAXB * HW];
__device__ unsigned long long g_kg[MAXB * HW];
__device__ unsigned long long g_kb[MAXB * HW];

__device__ __forceinline__ unsigned int fenc(float f) {
    unsigned int u = __float_as_uint(f);
    return (u & 0x80000000u) ? ~u : (u | 0x80000000u);
}

// One thread per (batch, triangle); 128-thread blocks (max CTA spread).
__global__ void __launch_bounds__(128)
raster_kernel(const float* __restrict__ vertices,
              const float* __restrict__ colors,
              const int*   __restrict__ triangles,
              int B, int ntri, int nver) {
    int idx = blockIdx.x * blockDim.x + threadIdx.x;
    if (idx >= B * ntri) return;
    int b = idx / ntri;
    int t = idx - b * ntri;

    // First L2 trip: 3 independent index loads.
    int i0 = __ldg(&triangles[t]);
    int i1 = __ldg(&triangles[ntri + t]);
    int i2 = __ldg(&triangles[2 * ntri + t]);

    // Second L2 trip: 18 independent gathers once indices land.
    const float* V = vertices + (size_t)b * 3 * nver;
    const float* C = colors   + (size_t)b * 3 * nver;
    float x0 = __ldg(&V[i0]),            x1 = __ldg(&V[i1]),            x2 = __ldg(&V[i2]);
    float y0 = __ldg(&V[nver + i0]),     y1 = __ldg(&V[nver + i1]),     y2 = __ldg(&V[nver + i2]);
    float z0 = __ldg(&V[2 * nver + i0]), z1 = __ldg(&V[2 * nver + i1]), z2 = __ldg(&V[2 * nver + i2]);
    float r0 = __ldg(&C[i0]),            r1 = __ldg(&C[i1]),            r2 = __ldg(&C[i2]);
    float g0 = __ldg(&C[nver + i0]),     g1 = __ldg(&C[nver + i1]),     g2 = __ldg(&C[nver + i2]);
    float b0 = __ldg(&C[2 * nver + i0]), b1 = __ldg(&C[2 * nver + i1]), b2 = __ldg(&C[2 * nver + i2]);

    float depth = ((z0 + z1) + z2) / 3.0f;
    float cr = ((r0 + r1) + r2) / 3.0f;
    float cg = ((g0 + g1) + g2) / 3.0f;
    float cb = ((b0 + b1) + b2) / 3.0f;

    float xmin = fminf(fminf(x0, x1), x2);
    float xmax = fmaxf(fmaxf(x0, x1), x2);
    float ymin = fminf(fminf(y0, y1), y2);
    float ymax = fmaxf(fmaxf(y0, y1), y2);

    // Match reference: max(ceil(min),0), min(floor(max), dim-1) in float, cast.
    int umin = (int)fmaxf(ceilf(xmin), 0.0f);
    int umax = (int)fminf(floorf(xmax), (float)(WW - 1));
    int vmin = (int)fmaxf(ceilf(ymin), 0.0f);
    int vmax = (int)fminf(floorf(ymax), (float)(HH - 1));
    if (umin > umax || vmin > vmax) return;

    unsigned long long dhi = (unsigned long long)fenc(depth) << 32;
    unsigned long long kr = dhi | __float_as_uint(cr);
    unsigned long long kg = dhi | __float_as_uint(cg);
    unsigned long long kb = dhi | __float_as_uint(cb);

    size_t pb = (size_t)b * HW;
    for (int v = vmin; v <= vmax; ++v) {
        size_t rowoff = pb + (size_t)v * WW;
        for (int u = umin; u <= umax; ++u) {
            atomicMax(&g_kr[rowoff + u], kr);   // return discarded -> REDG
            atomicMax(&g_kg[rowoff + u], kg);
            atomicMax(&g_kb[rowoff + u], kb);
        }
    }
}

// Four pixels per thread on the planar arrays: 6x LDG.128 (2 per channel, all
// independent), 6x STG.128 reset, branchless decode, 4x float4 output stores.
// HW % 4 == 0, so a pixel quad never straddles a batch or image plane.
__global__ void __launch_bounds__(256)
resolve_kernel(float* __restrict__ out, int B) {
    int g    = blockIdx.x * blockDim.x + threadIdx.x;   // pixel-quad id
    int ngrp = B * HW / 4;
    if (g >= ngrp) return;
    int p4  = g * 4;
    int b   = p4 / HW;
    int pix = p4 - b * HW;

    uint4* kr4 = reinterpret_cast<uint4*>(&g_kr[p4]);   // 4 keys = 2 uint4 each
    uint4* kg4 = reinterpret_cast<uint4*>(&g_kg[p4]);
    uint4* kb4 = reinterpret_cast<uint4*>(&g_kb[p4]);
    uint4 kra = __ldcg(kr4), krb = __ldcg(kr4 + 1);     // 6 independent loads
    uint4 kga = __ldcg(kg4), kgb = __ldcg(kg4 + 1);
    uint4 kba = __ldcg(kb4), kbb = __ldcg(kb4 + 1);
    uint4 z = make_uint4(0u, 0u, 0u, 0u);
    kr4[0] = z; kr4[1] = z;                             // restore zero invariant
    kg4[0] = z; kg4[1] = z;
    kb4[0] = z; kb4[1] = z;

    // key j: lo = float bits, hi = encoded depth (0 = uncovered)
    unsigned int rhi[4] = {kra.y, kra.w, krb.y, krb.w};
    unsigned int rlo[4] = {kra.x, kra.z, krb.x, krb.z};
    unsigned int glo[4] = {kga.x, kga.z, kgb.x, kgb.z};
    unsigned int blo[4] = {kba.x, kba.z, kbb.x, kbb.z};

    float4 m, c0, c1, c2;
    float* mf = &m.x; float* c0f = &c0.x; float* c1f = &c1.x; float* c2f = &c2.x;
#pragma unroll
    for (int j = 0; j < 4; ++j) {
        bool cov = (rhi[j] != 0u);
        mf[j]  = cov ? 1.0f : 0.0f;
        c0f[j] = cov ? __uint_as_float(rlo[j]) : 0.0f;
        c1f[j] = cov ? __uint_as_float(glo[j]) : 0.0f;
        c2f[j] = cov ? __uint_as_float(blo[j]) : 0.0f;
    }

    // Output layout: face_mask [B,1,H,W] then image [B,3,H,W]; 16B-aligned quads.
    *reinterpret_cast<float4*>(&out[(size_t)b * HW + pix]) = m;
    float* img = out + (size_t)B * HW;
    *reinterpret_cast<float4*>(&img[((size_t)b * 3 + 0) * HW + pix]) = c0;
    *reinterpret_cast<float4*>(&img[((size_t)b * 3 + 1) * HW + pix]) = c1;
    *reinterpret_cast<float4*>(&img[((size_t)b * 3 + 2) * HW + pix]) = c2;
}

extern "C" void kernel_launch(void* const* d_in, const int* in_sizes, int n_in,
                              void* d_out, int out_size) {
    const float* vertices  = (const float*)d_in[0];
    const float* colors    = (const float*)d_in[1];
    const int*   triangles = (const int*)d_in[2];

    int ntri = in_sizes[2] / 3;
    int B    = out_size / (4 * HW);
    int nver = in_sizes[0] / (3 * B);
    float* out = (float*)d_out;

    int nwork = B * ntri;
    raster_kernel<<<(nwork + 127) / 128, 128>>>(vertices, colors, triangles,
                                                B, ntri, nver);

    int ngrp = B * HW / 4;
    resolve_kernel<<<(ngrp + 255) / 256, 256>>>(out, B);
}

// round 13
// speedup vs baseline: 1.0701x; 1.0701x over previous
#include <cuda_runtime.h>
#include <stdint.h>

// Problem constants (fixed by the dataset problem).
#define HH 112
#define WW 112
#define HW (HH * WW)
#define MAXB 4   // scratch sized for up to 4 batches

// Planar per-pixel per-channel winner keys:
//   high 32 = order-preserving encoded flat depth
//   low  32 = raw float bits of that triangle's flat color for this channel
// atomicMax (return discarded -> REDG) selects max-depth triangle; payload
// rides along. 0 = "uncovered". Zero-initialized at module load; resolve
// re-zeros after consuming (invariant across graph replays) — no init kernel.
__device__ unsigned long long g_kr[MAXB * HW];
__device__ unsigned long long g_kg[MAXB * HW];
__device__ unsigned long long g_kb[MAXB * HW];

__device__ __forceinline__ unsigned int fenc(float f) {
    unsigned int u = __float_as_uint(f);
    return (u & 0x80000000u) ? ~u : (u | 0x80000000u);
}

// One thread per (batch, triangle); 128-thread blocks (max CTA spread).
__global__ void __launch_bounds__(128)
raster_kernel(const float* __restrict__ vertices,
              const float* __restrict__ colors,
              const int*   __restrict__ triangles,
              int B, int ntri, int nver) {
    int idx = blockIdx.x * blockDim.x + threadIdx.x;
    if (idx >= B * ntri) return;
    int b = idx / ntri;
    int t = idx - b * ntri;

    // First L2 trip: 3 independent index loads.
    int i0 = __ldg(&triangles[t]);
    int i1 = __ldg(&triangles[ntri + t]);
    int i2 = __ldg(&triangles[2 * ntri + t]);

    // Second L2 trip: 18 independent gathers once indices land.
    const float* V = vertices + (size_t)b * 3 * nver;
    const float* C = colors   + (size_t)b * 3 * nver;
    float x0 = __ldg(&V[i0]),            x1 = __ldg(&V[i1]),            x2 = __ldg(&V[i2]);
    float y0 = __ldg(&V[nver + i0]),     y1 = __ldg(&V[nver + i1]),     y2 = __ldg(&V[nver + i2]);
    float z0 = __ldg(&V[2 * nver + i0]), z1 = __ldg(&V[2 * nver + i1]), z2 = __ldg(&V[2 * nver + i2]);
    float r0 = __ldg(&C[i0]),            r1 = __ldg(&C[i1]),            r2 = __ldg(&C[i2]);
    float g0 = __ldg(&C[nver + i0]),     g1 = __ldg(&C[nver + i1]),     g2 = __ldg(&C[nver + i2]);
    float b0 = __ldg(&C[2 * nver + i0]), b1 = __ldg(&C[2 * nver + i1]), b2 = __ldg(&C[2 * nver + i2]);

    float depth = ((z0 + z1) + z2) / 3.0f;
    float cr = ((r0 + r1) + r2) / 3.0f;
    float cg = ((g0 + g1) + g2) / 3.0f;
    float cb = ((b0 + b1) + b2) / 3.0f;

    float xmin = fminf(fminf(x0, x1), x2);
    float xmax = fmaxf(fmaxf(x0, x1), x2);
    float ymin = fminf(fminf(y0, y1), y2);
    float ymax = fmaxf(fmaxf(y0, y1), y2);

    // Match reference: max(ceil(min),0), min(floor(max), dim-1) in float, cast.
    int umin = (int)fmaxf(ceilf(xmin), 0.0f);
    int umax = (int)fminf(floorf(xmax), (float)(WW - 1));
    int vmin = (int)fmaxf(ceilf(ymin), 0.0f);
    int vmax = (int)fminf(floorf(ymax), (float)(HH - 1));
    if (umin > umax || vmin > vmax) return;

    unsigned long long dhi = (unsigned long long)fenc(depth) << 32;
    unsigned long long kr = dhi | __float_as_uint(cr);
    unsigned long long kg = dhi | __float_as_uint(cg);
    unsigned long long kb = dhi | __float_as_uint(cb);

    size_t pb = (size_t)b * HW;
    for (int v = vmin; v <= vmax; ++v) {
        size_t rowoff = pb + (size_t)v * WW;
        for (int u = umin; u <= umax; ++u) {
            atomicMax(&g_kr[rowoff + u], kr);   // return discarded -> REDG
            atomicMax(&g_kg[rowoff + u], kg);
            atomicMax(&g_kb[rowoff + u], kb);
        }
    }
}

// Two pixels per thread on the planar arrays (measured-best per-thread shape),
// 128-thread blocks -> 98 CTAs (max spread): 3x LDG.128, 3x STG.128 reset,
// branchless decode, float2 coalesced output stores. HW is even, so a pixel
// pair never straddles a batch or image plane.
__global__ void __launch_bounds__(128)
resolve_kernel(float* __restrict__ out, int B) {
    int g    = blockIdx.x * blockDim.x + threadIdx.x;   // pixel-pair id
    int ngrp = B * HW / 2;
    if (g >= ngrp) return;
    int p2  = g * 2;
    int b   = p2 / HW;
    int pix = p2 - b * HW;

    uint4* kr2 = reinterpret_cast<uint4*>(&g_kr[p2]);   // 2 keys, 16B aligned
    uint4* kg2 = reinterpret_cast<uint4*>(&g_kg[p2]);
    uint4* kb2 = reinterpret_cast<uint4*>(&g_kb[p2]);
    uint4 akr = __ldcg(kr2);     // pix0: (.x lo, .y hi)   pix1: (.z lo, .w hi)
    uint4 akg = __ldcg(kg2);
    uint4 akb = __ldcg(kb2);
    uint4 z = make_uint4(0u, 0u, 0u, 0u);
    *kr2 = z;                    // restore zero invariant for next replay
    *kg2 = z;
    *kb2 = z;

    bool cov0 = (akr.y != 0u);
    bool cov1 = (akr.w != 0u);
    float2 m  = make_float2(cov0 ? 1.0f : 0.0f, cov1 ? 1.0f : 0.0f);
    float2 c0 = make_float2(cov0 ? __uint_as_float(akr.x) : 0.0f,
                            cov1 ? __uint_as_float(akr.z) : 0.0f);
    float2 c1 = make_float2(cov0 ? __uint_as_float(akg.x) : 0.0f,
                            cov1 ? __uint_as_float(akg.z) : 0.0f);
    float2 c2 = make_float2(cov0 ? __uint_as_float(akb.x) : 0.0f,
                            cov1 ? __uint_as_float(akb.z) : 0.0f);

    // Output layout: face_mask [B,1,H,W] then image [B,3,H,W]; 8B-aligned pairs.
    *reinterpret_cast<float2*>(&out[(size_t)b * HW + pix]) = m;
    float* img = out + (size_t)B * HW;
    *reinterpret_cast<float2*>(&img[((size_t)b * 3 + 0) * HW + pix]) = c0;
    *reinterpret_cast<float2*>(&img[((size_t)b * 3 + 1) * HW + pix]) = c1;
    *reinterpret_cast<float2*>(&img[((size_t)b * 3 + 2) * HW + pix]) = c2;
}

extern "C" void kernel_launch(void* const* d_in, const int* in_sizes, int n_in,
                              void* d_out, int out_size) {
    const float* vertices  = (const float*)d_in[0];
    const float* colors    = (const float*)d_in[1];
    const int*   triangles = (const int*)d_in[2];

    int ntri = in_sizes[2] / 3;
    int B    = out_size / (4 * HW);
    int nver = in_sizes[0] / (3 * B);
    float* out = (float*)d_out;

    int nwork = B * ntri;
    raster_kernel<<<(nwork + 127) / 128, 128>>>(vertices, colors, triangles,
                                                B, ntri, nver);

    int ngrp = B * HW / 2;
    resolve_kernel<<<(ngrp + 127) / 128, 128>>>(out, B);
}